// round 3
// baseline (speedup 1.0000x reference)
#include <cuda_runtime.h>
#include <math.h>

// Problem constants
#define B_  4
#define N_  8192
#define PTS (B_ * N_)      // 32768
#define KNN 16
#define W0_ 64
#define W1_ 128
#define W2_ 256

// ---------------- scratch (static __device__ allowed) ----------------
__device__ float4 g_cxx[PTS];                 // coords + xx
__device__ float  g_f0 [PTS * W0_];
__device__ int    g_idx[PTS * KNN];
__device__ float  g_wcat1[W0_ * (2 * W1_)];   // 64 x 256
__device__ float  g_bias1[2 * W1_];
__device__ float  g_c1 [PTS * (2 * W1_)];     // [t1 | s1]
__device__ float  g_f1 [PTS * W1_];
__device__ float  g_wcat2[W1_ * (2 * W2_)];   // 128 x 512
__device__ float  g_bias2[2 * W2_];
__device__ float  g_c2 [PTS * (2 * W2_)];     // [t2 | s2]
__device__ float  g_f2 [PTS * W2_];
__device__ unsigned int g_g0[B_ * W2_];       // global max (bits)
__device__ float  g_ghb[B_ * W2_];            // per-batch head1 bias row
__device__ float  g_h  [PTS * W2_];

// ---------------- prep kernels ----------------
__global__ void prep1_kernel(const float* __restrict__ b1w, const float* __restrict__ b1b) {
    int i = blockIdx.x * 256 + threadIdx.x;
    if (i < W0_ * W1_) {
        int d = i >> 7, o = i & 127;
        float wa = b1w[d * W1_ + o];
        float wb = b1w[(W0_ + d) * W1_ + o];
        g_wcat1[d * (2 * W1_) + o]        = wa - wb;
        g_wcat1[d * (2 * W1_) + W1_ + o]  = wb;
    }
    if (i < 2 * W1_) g_bias1[i] = (i < W1_) ? b1b[i] : 0.f;
}

__global__ void prep2_kernel(const float* __restrict__ b2w, const float* __restrict__ b2b) {
    int i = blockIdx.x * 256 + threadIdx.x;
    if (i < W1_ * W2_) {
        int d = i >> 8, o = i & 255;
        float wa = b2w[d * W2_ + o];
        float wb = b2w[(W1_ + d) * W2_ + o];
        g_wcat2[d * (2 * W2_) + o]        = wa - wb;
        g_wcat2[d * (2 * W2_) + W2_ + o]  = wb;
    }
    if (i < 2 * W2_) g_bias2[i] = (i < W2_) ? b2b[i] : 0.f;
    if (i < B_ * W2_) g_g0[i] = 0u;   // re-zero every call (deterministic)
}

// ---------------- stem: coords, xx, f0 ----------------
__global__ void stem_kernel(const float* __restrict__ x,
                            const float* __restrict__ sw, const float* __restrict__ sb,
                            const float* __restrict__ ha, const float* __restrict__ hb,
                            const float* __restrict__ hc) {
    __shared__ float xs[4][4];
    __shared__ float ws[4 * 64];
    __shared__ float bs[64];
    int tid = threadIdx.x;
    ws[tid] = sw[tid];                 // 256 == 4*64
    if (tid < 64) bs[tid] = sb[tid];
    int p = tid >> 6, o = tid & 63;
    int point = blockIdx.x * 4 + p;
    if (o < 4) xs[p][o] = x[point * 4 + o];
    __syncthreads();
    float acc = bs[o];
    #pragma unroll
    for (int i = 0; i < 4; i++) acc = fmaf(xs[p][i], ws[i * 64 + o], acc);
    g_f0[point * W0_ + o] = fmaxf(acc, 0.f);
    if (o == 0) {
        float x0 = xs[p][0], x1 = xs[p][1];
        float z = __fadd_rn(__fadd_rn(__fmul_rn(*ha, xs[p][2]), __fmul_rn(*hb, xs[p][3])), *hc);
        float xx = __fadd_rn(__fadd_rn(__fmul_rn(x0, x0), __fmul_rn(x1, x1)), __fmul_rn(z, z));
        g_cxx[point] = make_float4(x0, x1, z, xx);
    }
}

// ---------------- kNN: register top-16 insertion ----------------
#define KTS 512
__global__ __launch_bounds__(64) void knn_kernel() {
    __shared__ float4 tile[KTS];
    int q = blockIdx.x * 64 + threadIdx.x;
    int base = (q >> 13) << 13;          // batch start
    float4 cq = g_cxx[q];
    float bd[KNN];
    int   bi[KNN];
    #pragma unroll
    for (int i = 0; i < KNN; i++) { bd[i] = 3.4e38f; bi[i] = 0; }
    for (int t0 = 0; t0 < N_; t0 += KTS) {
        __syncthreads();
        #pragma unroll
        for (int i = 0; i < KTS / 64; i++) tile[threadIdx.x + i * 64] = g_cxx[base + t0 + threadIdx.x + i * 64];
        __syncthreads();
        for (int j = 0; j < KTS; j++) {
            float4 cm = tile[j];
            float dot = fmaf(cq.z, cm.z, fmaf(cq.y, cm.y, __fmul_rn(cq.x, cm.x)));
            float d = __fsub_rn(__fadd_rn(cq.w, cm.w), __fmul_rn(2.f, dot));
            d = fmaxf(d, 0.f);
            if (d < bd[KNN - 1]) {
                float dd = d; int ii = t0 + j;
                #pragma unroll
                for (int s = 0; s < KNN; s++) {
                    if (dd < bd[s]) {
                        float td = bd[s]; int ti = bi[s];
                        bd[s] = dd; bi[s] = ii; dd = td; ii = ti;
                    }
                }
            }
        }
    }
    #pragma unroll
    for (int i = 0; i < KNN; i++) g_idx[q * KNN + i] = base + bi[i];
}

// ---------------- tiled FFMA GEMM: C[M,N] = A[M,K] @ W[K,N] (+bias, +rowbias, relu) ----------------
// BM=128, BN=64, BK=16, 256 threads, 8x4 per thread. M=32768, K,N multiples of 16/64.
__global__ __launch_bounds__(256) void gemm_kernel(
        const float* __restrict__ A, const float* __restrict__ W,
        const float* __restrict__ bias, const float* __restrict__ rowbias,
        float* __restrict__ C, int K, int N, int do_relu) {
    const int BM = 128, BN = 64, BK = 16;
    __shared__ float As[BK][BM];
    __shared__ float Ws[BK][BN];
    int tid = threadIdx.x;
    int tx = tid & 15, ty = tid >> 4;
    int rowTile = blockIdx.y * BM;
    int colTile = blockIdx.x * BN;
    float acc[8][4];
    #pragma unroll
    for (int i = 0; i < 8; i++)
        #pragma unroll
        for (int j = 0; j < 4; j++) acc[i][j] = 0.f;

    for (int k0 = 0; k0 < K; k0 += BK) {
        {   // A tile: 128 rows x 16 k, thread loads 8 (two float4), store transposed
            int r  = tid >> 1;
            int kk = (tid & 1) * 8;
            const float* src = A + (size_t)(rowTile + r) * K + k0 + kk;
            float4 v0 = *(const float4*)(src);
            float4 v1 = *(const float4*)(src + 4);
            As[kk + 0][r] = v0.x; As[kk + 1][r] = v0.y; As[kk + 2][r] = v0.z; As[kk + 3][r] = v0.w;
            As[kk + 4][r] = v1.x; As[kk + 5][r] = v1.y; As[kk + 6][r] = v1.z; As[kk + 7][r] = v1.w;
        }
        {   // W tile: 16 x 64, thread loads 4
            int kw = tid >> 4;
            int c  = (tid & 15) * 4;
            float4 v = *(const float4*)(W + (size_t)(k0 + kw) * N + colTile + c);
            Ws[kw][c] = v.x; Ws[kw][c + 1] = v.y; Ws[kw][c + 2] = v.z; Ws[kw][c + 3] = v.w;
        }
        __syncthreads();
        #pragma unroll
        for (int kk = 0; kk < BK; kk++) {
            float a[8], b[4];
            #pragma unroll
            for (int i = 0; i < 8; i++) a[i] = As[kk][ty * 8 + i];
            #pragma unroll
            for (int j = 0; j < 4; j++) b[j] = Ws[kk][tx * 4 + j];
            #pragma unroll
            for (int i = 0; i < 8; i++)
                #pragma unroll
                for (int j = 0; j < 4; j++) acc[i][j] = fmaf(a[i], b[j], acc[i][j]);
        }
        __syncthreads();
    }

    int batchoff = (rowTile >> 13) * N;   // batch constant per 128-row tile
    float bv[4];
    #pragma unroll
    for (int j = 0; j < 4; j++) {
        int col = colTile + tx * 4 + j;
        float v = bias ? bias[col] : 0.f;
        if (rowbias) v += rowbias[batchoff + col];
        bv[j] = v;
    }
    #pragma unroll
    for (int i = 0; i < 8; i++) {
        int row = rowTile + ty * 8 + i;
        float4 o;
        float v0 = acc[i][0] + bv[0], v1 = acc[i][1] + bv[1];
        float v2 = acc[i][2] + bv[2], v3 = acc[i][3] + bv[3];
        if (do_relu) { v0 = fmaxf(v0, 0.f); v1 = fmaxf(v1, 0.f); v2 = fmaxf(v2, 0.f); v3 = fmaxf(v3, 0.f); }
        o.x = v0; o.y = v1; o.z = v2; o.w = v3;
        *(float4*)(C + (size_t)row * N + colTile + tx * 4) = o;
    }
}

// ---------------- combine: out[n][o] = max_k relu(t[n][o] + s[idx][o] + dp . wc[:,o]) ----------------
__global__ void combine_kernel(const float* __restrict__ C, const float* __restrict__ wc,
                               float* __restrict__ out, int F) {
    int n = blockIdx.x;
    int o = threadIdx.x;
    __shared__ int   sidx[KNN];
    __shared__ float sdp[KNN][3];
    if (o < KNN) {
        int m = g_idx[n * KNN + o];
        sidx[o] = m;
        float4 cm = g_cxx[m];
        float4 cn = g_cxx[n];
        sdp[o][0] = cm.x - cn.x; sdp[o][1] = cm.y - cn.y; sdp[o][2] = cm.z - cn.z;
    }
    __syncthreads();
    int twoF = 2 * F;
    float tv = C[(size_t)n * twoF + o];
    float w0 = wc[o], w1 = wc[F + o], w2 = wc[2 * F + o];
    float best = 0.f;
    #pragma unroll 4
    for (int k = 0; k < KNN; k++) {
        int m = sidx[k];
        float sv = C[(size_t)m * twoF + F + o];
        float v = tv + sv;
        v = fmaf(sdp[k][0], w0, v);
        v = fmaf(sdp[k][1], w1, v);
        v = fmaf(sdp[k][2], w2, v);
        best = fmaxf(best, v);
    }
    out[(size_t)n * F + o] = best;
}

// ---------------- global max over points ----------------
__global__ void gmax_kernel() {
    int b  = blockIdx.x >> 5;
    int sp = blockIdx.x & 31;
    int o  = threadIdx.x;
    float m = 0.f;
    int n0 = b * N_ + sp * 256;
    for (int i = 0; i < 256; i++) m = fmaxf(m, g_f2[(size_t)(n0 + i) * W2_ + o]);
    atomicMax(&g_g0[b * W2_ + o], __float_as_uint(m));   // f2 >= 0
}

// ---------------- per-batch global MLP + head1 g-bias ----------------
__global__ void headg_kernel(const float* __restrict__ gw, const float* __restrict__ gb,
                             const float* __restrict__ h1w, const float* __restrict__ h1b) {
    int b = blockIdx.x;
    int o = threadIdx.x;
    __shared__ float s0[W2_], s1[W2_];
    s0[o] = __uint_as_float(g_g0[b * W2_ + o]);
    __syncthreads();
    float acc = gb[o];
    for (int d = 0; d < W2_; d++) acc = fmaf(s0[d], gw[d * W2_ + o], acc);
    s1[o] = fmaxf(acc, 0.f);
    __syncthreads();
    float acc2 = h1b[o];
    for (int d = 0; d < W2_; d++) acc2 = fmaf(s1[d], h1w[(W2_ + d) * W2_ + o], acc2);
    g_ghb[b * W2_ + o] = acc2;
}

// ---------------- head2 + height bias ----------------
__global__ __launch_bounds__(128) void head2_kernel(const float* __restrict__ w2, const float* __restrict__ b2,
                                                    const float* __restrict__ x,
                                                    const float* __restrict__ thresh, const float* __restrict__ sharp,
                                                    const float* __restrict__ scale, float* __restrict__ out) {
    int warp = threadIdx.x >> 5, lane = threadIdx.x & 31;
    int n = blockIdx.x * 4 + warp;
    float a0 = 0.f, a1 = 0.f, a2 = 0.f;
    #pragma unroll
    for (int i = 0; i < 8; i++) {
        int d = lane + i * 32;
        float hv = g_h[(size_t)n * W2_ + d];
        a0 = fmaf(hv, w2[d * 3 + 0], a0);
        a1 = fmaf(hv, w2[d * 3 + 1], a1);
        a2 = fmaf(hv, w2[d * 3 + 2], a2);
    }
    #pragma unroll
    for (int off = 16; off; off >>= 1) {
        a0 += __shfl_down_sync(0xffffffffu, a0, off);
        a1 += __shfl_down_sync(0xffffffffu, a1, off);
        a2 += __shfl_down_sync(0xffffffffu, a2, off);
    }
    if (lane == 0) {
        float hag = x[n * 4 + 3];
        float hb = (*scale) / (1.f + expf((*sharp) * (hag - (*thresh))));
        out[n * 3 + 0] = a0 + b2[0] + hb;
        out[n * 3 + 1] = a1 + b2[1];
        out[n * 3 + 2] = a2 + b2[2];
    }
}

// ---------------- launcher ----------------
extern "C" void kernel_launch(void* const* d_in, const int* in_sizes, int n_in,
                              void* d_out, int out_size) {
    const float* x       = (const float*)d_in[0];
    const float* hmix_a  = (const float*)d_in[1];
    const float* hmix_b  = (const float*)d_in[2];
    const float* hmix_c  = (const float*)d_in[3];
    const float* stem_w  = (const float*)d_in[4];
    const float* stem_b  = (const float*)d_in[5];
    const float* b1_w    = (const float*)d_in[6];
    const float* b1_b    = (const float*)d_in[7];
    const float* b2_w    = (const float*)d_in[8];
    const float* b2_b    = (const float*)d_in[9];
    const float* glob_w  = (const float*)d_in[10];
    const float* glob_b  = (const float*)d_in[11];
    const float* head1_w = (const float*)d_in[12];
    const float* head1_b = (const float*)d_in[13];
    const float* head2_w = (const float*)d_in[14];
    const float* head2_b = (const float*)d_in[15];
    const float* thresh  = (const float*)d_in[16];
    const float* sharp   = (const float*)d_in[17];
    const float* scale   = (const float*)d_in[18];
    float* out = (float*)d_out;

    float4* cxx;   cudaGetSymbolAddress((void**)&cxx,   g_cxx);
    float*  f0;    cudaGetSymbolAddress((void**)&f0,    g_f0);
    float*  wcat1; cudaGetSymbolAddress((void**)&wcat1, g_wcat1);
    float*  bias1; cudaGetSymbolAddress((void**)&bias1, g_bias1);
    float*  c1;    cudaGetSymbolAddress((void**)&c1,    g_c1);
    float*  f1;    cudaGetSymbolAddress((void**)&f1,    g_f1);
    float*  wcat2; cudaGetSymbolAddress((void**)&wcat2, g_wcat2);
    float*  bias2; cudaGetSymbolAddress((void**)&bias2, g_bias2);
    float*  c2;    cudaGetSymbolAddress((void**)&c2,    g_c2);
    float*  f2;    cudaGetSymbolAddress((void**)&f2,    g_f2);
    float*  ghb;   cudaGetSymbolAddress((void**)&ghb,   g_ghb);
    float*  h;     cudaGetSymbolAddress((void**)&h,     g_h);

    // 1. prep (weight restructure + zero g0)
    prep1_kernel<<<(W0_ * W1_ + 255) / 256, 256>>>(b1_w, b1_b);
    prep2_kernel<<<(W1_ * W2_ + 255) / 256, 256>>>(b2_w, b2_b);
    // 2. stem + coords
    stem_kernel<<<PTS / 4, 256>>>(x, stem_w, stem_b, hmix_a, hmix_b, hmix_c);
    // 3. kNN
    knn_kernel<<<PTS / 64, 64>>>();
    // 4. agg1 matvecs: c1 = f0 @ wcat1 (+bias1)
    {
        dim3 grid((2 * W1_) / 64, PTS / 128);
        gemm_kernel<<<grid, 256>>>(f0, wcat1, bias1, nullptr, c1, W0_, 2 * W1_, 0);
    }
    // 5. agg1 combine -> f1
    combine_kernel<<<PTS, W1_>>>(c1, b1_w + (2 * W0_) * W1_, f1, W1_);
    // 6. agg2 matvecs: c2 = f1 @ wcat2 (+bias2)
    {
        dim3 grid((2 * W2_) / 64, PTS / 128);
        gemm_kernel<<<grid, 256>>>(f1, wcat2, bias2, nullptr, c2, W1_, 2 * W2_, 0);
    }
    // 7. agg2 combine -> f2
    combine_kernel<<<PTS, W2_>>>(c2, b2_w + (2 * W1_) * W2_, f2, W2_);
    // 8. global max
    gmax_kernel<<<B_ * 32, 256>>>();
    // 9. per-batch glob MLP + g-part of head1 bias
    headg_kernel<<<B_, W2_>>>(glob_w, glob_b, head1_w, head1_b);
    // 10. head1: h = relu(f2 @ head1_w[0:256] + ghb[batch])
    {
        dim3 grid(W2_ / 64, PTS / 128);
        gemm_kernel<<<grid, 256>>>(f2, head1_w, nullptr, ghb, h, W2_, W2_, 1);
    }
    // 11. head2 + height bias
    head2_kernel<<<PTS / 4, 128>>>(head2_w, head2_b, x, thresh, sharp, scale, out);
}

// round 5
// speedup vs baseline: 1.2027x; 1.2027x over previous
#include <cuda_runtime.h>
#include <math.h>

// Problem constants
#define B_  4
#define N_  8192
#define PTS (B_ * N_)      // 32768
#define KNN 16
#define W0_ 64
#define W1_ 128
#define W2_ 256

#define SLICES 4
#define SLICE_N (N_ / SLICES)   // 2048
#define PTILE 512

// ---------------- scratch (static __device__ allowed) ----------------
__device__ float4 g_cxx[PTS];                 // coords + xx
__device__ float  g_f0 [PTS * W0_];
__device__ int    g_idx[PTS * KNN];
__device__ float  g_pd [PTS * SLICES * KNN];  // per-slice partial top-16 dists
__device__ int    g_pi [PTS * SLICES * KNN];  // per-slice partial top-16 idx
__device__ float  g_wcat1[W0_ * (2 * W1_)];   // 64 x 256
__device__ float  g_bias1[2 * W1_];
__device__ float  g_c1 [PTS * (2 * W1_)];     // [t1 | s1]
__device__ float  g_f1 [PTS * W1_];
__device__ float  g_wcat2[W1_ * (2 * W2_)];   // 128 x 512
__device__ float  g_bias2[2 * W2_];
__device__ float  g_c2 [PTS * (2 * W2_)];     // [t2 | s2]
__device__ float  g_f2 [PTS * W2_];
__device__ unsigned int g_g0[B_ * W2_];       // global max (bits)
__device__ float  g_ghb[B_ * W2_];            // per-batch head1 bias row
__device__ float  g_h  [PTS * W2_];

// ---------------- f32x2 helpers ----------------
__device__ __forceinline__ unsigned long long pack_dup(float v) {
    unsigned long long r;
    asm("mov.b64 %0, {%1, %1};" : "=l"(r) : "r"(__float_as_uint(v)));
    return r;
}
__device__ __forceinline__ void fma2(unsigned long long& d, unsigned long long a,
                                     unsigned long long b) {
    asm("fma.rn.f32x2 %0, %1, %2, %0;" : "+l"(d) : "l"(a), "l"(b));
}
__device__ __forceinline__ void unpack2(unsigned long long v, float& lo, float& hi) {
    unsigned int l, h;
    asm("mov.b64 {%0, %1}, %2;" : "=r"(l), "=r"(h) : "l"(v));
    lo = __uint_as_float(l); hi = __uint_as_float(h);
}

// ---------------- prep kernels ----------------
__global__ void prep1_kernel(const float* __restrict__ b1w, const float* __restrict__ b1b) {
    int i = blockIdx.x * 256 + threadIdx.x;
    if (i < W0_ * W1_) {
        int d = i >> 7, o = i & 127;
        float wa = b1w[d * W1_ + o];
        float wb = b1w[(W0_ + d) * W1_ + o];
        g_wcat1[d * (2 * W1_) + o]        = wa - wb;
        g_wcat1[d * (2 * W1_) + W1_ + o]  = wb;
    }
    if (i < 2 * W1_) g_bias1[i] = (i < W1_) ? b1b[i] : 0.f;
}

__global__ void prep2_kernel(const float* __restrict__ b2w, const float* __restrict__ b2b) {
    int i = blockIdx.x * 256 + threadIdx.x;
    if (i < W1_ * W2_) {
        int d = i >> 8, o = i & 255;
        float wa = b2w[d * W2_ + o];
        float wb = b2w[(W1_ + d) * W2_ + o];
        g_wcat2[d * (2 * W2_) + o]        = wa - wb;
        g_wcat2[d * (2 * W2_) + W2_ + o]  = wb;
    }
    if (i < 2 * W2_) g_bias2[i] = (i < W2_) ? b2b[i] : 0.f;
    if (i < B_ * W2_) g_g0[i] = 0u;   // re-zero every call (deterministic)
}

// ---------------- stem: coords, xx, f0 ----------------
__global__ void stem_kernel(const float* __restrict__ x,
                            const float* __restrict__ sw, const float* __restrict__ sb,
                            const float* __restrict__ ha, const float* __restrict__ hb,
                            const float* __restrict__ hc) {
    __shared__ float xs[4][4];
    __shared__ float ws[4 * 64];
    __shared__ float bs[64];
    int tid = threadIdx.x;
    ws[tid] = sw[tid];                 // 256 == 4*64
    if (tid < 64) bs[tid] = sb[tid];
    int p = tid >> 6, o = tid & 63;
    int point = blockIdx.x * 4 + p;
    if (o < 4) xs[p][o] = x[point * 4 + o];
    __syncthreads();
    float acc = bs[o];
    #pragma unroll
    for (int i = 0; i < 4; i++) acc = fmaf(xs[p][i], ws[i * 64 + o], acc);
    g_f0[point * W0_ + o] = fmaxf(acc, 0.f);
    if (o == 0) {
        float x0 = xs[p][0], x1 = xs[p][1];
        float z = __fadd_rn(__fadd_rn(__fmul_rn(*ha, xs[p][2]), __fmul_rn(*hb, xs[p][3])), *hc);
        float xx = __fadd_rn(__fadd_rn(__fmul_rn(x0, x0), __fmul_rn(x1, x1)), __fmul_rn(z, z));
        g_cxx[point] = make_float4(x0, x1, z, xx);
    }
}

// ---------------- kNN part: each thread scans one 2048-candidate slice ----------------
// Ranks on e = cm.w - 2*dot (constant shift of true dist per query; ordering identical).
__global__ __launch_bounds__(128) void knn_part_kernel() {
    __shared__ float4 tile[PTILE];
    int q = blockIdx.x * 128 + threadIdx.x;
    int s = blockIdx.y;
    int base = (q >> 13) << 13;          // batch start
    int c0 = base + s * SLICE_N;
    float4 cq = g_cxx[q];
    float bd[KNN];
    int   bi[KNN];
    #pragma unroll
    for (int i = 0; i < KNN; i++) { bd[i] = 3.4e38f; bi[i] = 0; }
    for (int t0 = 0; t0 < SLICE_N; t0 += PTILE) {
        __syncthreads();
        #pragma unroll
        for (int i = 0; i < PTILE / 128; i++)
            tile[threadIdx.x + i * 128] = g_cxx[c0 + t0 + threadIdx.x + i * 128];
        __syncthreads();
        #pragma unroll 4
        for (int j = 0; j < PTILE; j++) {
            float4 cm = tile[j];
            float dot = fmaf(cq.z, cm.z, fmaf(cq.y, cm.y, cq.x * cm.x));
            float e = fmaf(-2.f, dot, cm.w);
            if (e < bd[KNN - 1]) {
                float dd = e; int ii = c0 + t0 + j;
                #pragma unroll
                for (int t = 0; t < KNN; t++) {
                    if (dd < bd[t]) {
                        float td = bd[t]; int ti = bi[t];
                        bd[t] = dd; bi[t] = ii; dd = td; ii = ti;
                    }
                }
            }
        }
    }
    size_t off = ((size_t)q * SLICES + s) * KNN;
    #pragma unroll
    for (int i = 0; i < KNN; i++) { g_pd[off + i] = bd[i]; g_pi[off + i] = bi[i]; }
}

// ---------------- kNN merge: 4 sorted 16-lists -> top-16 ----------------
// Slices processed in ascending-index order; strict < keeps the earlier (lower-index)
// candidate on ties, matching top_k stability.
__global__ __launch_bounds__(128) void knn_merge_kernel() {
    int q = blockIdx.x * 128 + threadIdx.x;
    float bd[KNN];
    int   bi[KNN];
    #pragma unroll
    for (int i = 0; i < KNN; i++) { bd[i] = 3.4e38f; bi[i] = 0; }
    #pragma unroll
    for (int s = 0; s < SLICES; s++) {
        size_t off = ((size_t)q * SLICES + s) * KNN;
        for (int k = 0; k < KNN; k++) {
            float d = g_pd[off + k];
            if (d >= bd[KNN - 1]) break;     // sorted list -> rest can't insert
            int ii = g_pi[off + k];
            float dd = d;
            #pragma unroll
            for (int t = 0; t < KNN; t++) {
                if (dd < bd[t]) {
                    float td = bd[t]; int ti = bi[t];
                    bd[t] = dd; bi[t] = ii; dd = td; ii = ti;
                }
            }
        }
    }
    #pragma unroll
    for (int i = 0; i < KNN; i++) g_idx[q * KNN + i] = bi[i];
}

// ---------------- tiled GEMM with f32x2 packed FMA ----------------
// C[M,N] = A[M,K] @ W[K,N] (+bias, +rowbias, relu). BM=128, BN=64, BK=16,
// 256 threads, 8x4 per thread, accumulator packed pairwise along M.
__global__ __launch_bounds__(256) void gemm_kernel(
        const float* __restrict__ A, const float* __restrict__ W,
        const float* __restrict__ bias, const float* __restrict__ rowbias,
        float* __restrict__ C, int K, int N, int do_relu) {
    const int BM = 128, BN = 64, BK = 16;
    __shared__ float As[BK][BM];
    __shared__ float Ws[BK][BN];
    int tid = threadIdx.x;
    int tx = tid & 15, ty = tid >> 4;
    int rowTile = blockIdx.y * BM;
    int colTile = blockIdx.x * BN;
    unsigned long long acc2[4][4];     // [i-pair][j], lo = row 2*i2, hi = row 2*i2+1
    #pragma unroll
    for (int i = 0; i < 4; i++)
        #pragma unroll
        for (int j = 0; j < 4; j++) acc2[i][j] = 0ull;

    for (int k0 = 0; k0 < K; k0 += BK) {
        {   // A tile: 128 rows x 16 k, thread loads 8 (two float4), store transposed
            int r  = tid >> 1;
            int kk = (tid & 1) * 8;
            const float* src = A + (size_t)(rowTile + r) * K + k0 + kk;
            float4 v0 = *(const float4*)(src);
            float4 v1 = *(const float4*)(src + 4);
            As[kk + 0][r] = v0.x; As[kk + 1][r] = v0.y; As[kk + 2][r] = v0.z; As[kk + 3][r] = v0.w;
            As[kk + 4][r] = v1.x; As[kk + 5][r] = v1.y; As[kk + 6][r] = v1.z; As[kk + 7][r] = v1.w;
        }
        {   // W tile: 16 x 64, thread loads 4
            int kw = tid >> 4;
            int c  = (tid & 15) * 4;
            float4 v = *(const float4*)(W + (size_t)(k0 + kw) * N + colTile + c);
            Ws[kw][c] = v.x; Ws[kw][c + 1] = v.y; Ws[kw][c + 2] = v.z; Ws[kw][c + 3] = v.w;
        }
        __syncthreads();
        #pragma unroll
        for (int kk = 0; kk < BK; kk++) {
            unsigned long long a2[4];
            #pragma unroll
            for (int i2 = 0; i2 < 4; i2++)
                a2[i2] = *(const unsigned long long*)&As[kk][ty * 8 + i2 * 2];
            #pragma unroll
            for (int j = 0; j < 4; j++) {
                unsigned long long b2 = pack_dup(Ws[kk][tx * 4 + j]);
                #pragma unroll
                for (int i2 = 0; i2 < 4; i2++) fma2(acc2[i2][j], a2[i2], b2);
            }
        }
        __syncthreads();
    }

    int batchoff = (rowTile >> 13) * N;   // batch constant per 128-row tile
    float bv[4];
    #pragma unroll
    for (int j = 0; j < 4; j++) {
        int col = colTile + tx * 4 + j;
        float v = bias ? bias[col] : 0.f;
        if (rowbias) v += rowbias[batchoff + col];
        bv[j] = v;
    }
    #pragma unroll
    for (int i2 = 0; i2 < 4; i2++) {
        float lo[4], hi[4];
        #pragma unroll
        for (int j = 0; j < 4; j++) {
            unpack2(acc2[i2][j], lo[j], hi[j]);
            lo[j] += bv[j]; hi[j] += bv[j];
            if (do_relu) { lo[j] = fmaxf(lo[j], 0.f); hi[j] = fmaxf(hi[j], 0.f); }
        }
        int r0 = rowTile + ty * 8 + i2 * 2;
        float4 o0 = make_float4(lo[0], lo[1], lo[2], lo[3]);
        float4 o1 = make_float4(hi[0], hi[1], hi[2], hi[3]);
        *(float4*)(C + (size_t)r0 * N + colTile + tx * 4) = o0;
        *(float4*)(C + (size_t)(r0 + 1) * N + colTile + tx * 4) = o1;
    }
}

// ---------------- combine: out[n][o] = max_k relu(t[n][o] + s[idx][o] + dp . wc[:,o]) ----------------
__global__ void combine_kernel(const float* __restrict__ C, const float* __restrict__ wc,
                               float* __restrict__ out, int F) {
    int n = blockIdx.x;
    int o = threadIdx.x;
    __shared__ int   sidx[KNN];
    __shared__ float sdp[KNN][3];
    if (o < KNN) {
        int m = g_idx[n * KNN + o];
        sidx[o] = m;
        float4 cm = g_cxx[m];
        float4 cn = g_cxx[n];
        sdp[o][0] = cm.x - cn.x; sdp[o][1] = cm.y - cn.y; sdp[o][2] = cm.z - cn.z;
    }
    __syncthreads();
    int twoF = 2 * F;
    float tv = C[(size_t)n * twoF + o];
    float w0 = wc[o], w1 = wc[F + o], w2 = wc[2 * F + o];
    float best = 0.f;
    #pragma unroll 4
    for (int k = 0; k < KNN; k++) {
        int m = sidx[k];
        float sv = C[(size_t)m * twoF + F + o];
        float v = tv + sv;
        v = fmaf(sdp[k][0], w0, v);
        v = fmaf(sdp[k][1], w1, v);
        v = fmaf(sdp[k][2], w2, v);
        best = fmaxf(best, v);
    }
    out[(size_t)n * F + o] = best;
}

// ---------------- global max over points ----------------
__global__ void gmax_kernel() {
    int b  = blockIdx.x >> 5;
    int sp = blockIdx.x & 31;
    int o  = threadIdx.x;
    float m = 0.f;
    int n0 = b * N_ + sp * 256;
    for (int i = 0; i < 256; i++) m = fmaxf(m, g_f2[(size_t)(n0 + i) * W2_ + o]);
    atomicMax(&g_g0[b * W2_ + o], __float_as_uint(m));   // f2 >= 0
}

// ---------------- per-batch global MLP + head1 g-bias ----------------
__global__ void headg_kernel(const float* __restrict__ gw, const float* __restrict__ gb,
                             const float* __restrict__ h1w, const float* __restrict__ h1b) {
    int b = blockIdx.x;
    int o = threadIdx.x;
    __shared__ float s0[W2_], s1[W2_];
    s0[o] = __uint_as_float(g_g0[b * W2_ + o]);
    __syncthreads();
    float acc = gb[o];
    for (int d = 0; d < W2_; d++) acc = fmaf(s0[d], gw[d * W2_ + o], acc);
    s1[o] = fmaxf(acc, 0.f);
    __syncthreads();
    float acc2 = h1b[o];
    for (int d = 0; d < W2_; d++) acc2 = fmaf(s1[d], h1w[(W2_ + d) * W2_ + o], acc2);
    g_ghb[b * W2_ + o] = acc2;
}

// ---------------- head2 + height bias ----------------
__global__ __launch_bounds__(128) void head2_kernel(const float* __restrict__ w2, const float* __restrict__ b2,
                                                    const float* __restrict__ x,
                                                    const float* __restrict__ thresh, const float* __restrict__ sharp,
                                                    const float* __restrict__ scale, float* __restrict__ out) {
    int warp = threadIdx.x >> 5, lane = threadIdx.x & 31;
    int n = blockIdx.x * 4 + warp;
    float a0 = 0.f, a1 = 0.f, a2 = 0.f;
    #pragma unroll
    for (int i = 0; i < 8; i++) {
        int d = lane + i * 32;
        float hv = g_h[(size_t)n * W2_ + d];
        a0 = fmaf(hv, w2[d * 3 + 0], a0);
        a1 = fmaf(hv, w2[d * 3 + 1], a1);
        a2 = fmaf(hv, w2[d * 3 + 2], a2);
    }
    #pragma unroll
    for (int off = 16; off; off >>= 1) {
        a0 += __shfl_down_sync(0xffffffffu, a0, off);
        a1 += __shfl_down_sync(0xffffffffu, a1, off);
        a2 += __shfl_down_sync(0xffffffffu, a2, off);
    }
    if (lane == 0) {
        float hag = x[n * 4 + 3];
        float hb = (*scale) / (1.f + expf((*sharp) * (hag - (*thresh))));
        out[n * 3 + 0] = a0 + b2[0] + hb;
        out[n * 3 + 1] = a1 + b2[1];
        out[n * 3 + 2] = a2 + b2[2];
    }
}

// ---------------- launcher ----------------
extern "C" void kernel_launch(void* const* d_in, const int* in_sizes, int n_in,
                              void* d_out, int out_size) {
    const float* x       = (const float*)d_in[0];
    const float* hmix_a  = (const float*)d_in[1];
    const float* hmix_b  = (const float*)d_in[2];
    const float* hmix_c  = (const float*)d_in[3];
    const float* stem_w  = (const float*)d_in[4];
    const float* stem_b  = (const float*)d_in[5];
    const float* b1_w    = (const float*)d_in[6];
    const float* b1_b    = (const float*)d_in[7];
    const float* b2_w    = (const float*)d_in[8];
    const float* b2_b    = (const float*)d_in[9];
    const float* glob_w  = (const float*)d_in[10];
    const float* glob_b  = (const float*)d_in[11];
    const float* head1_w = (const float*)d_in[12];
    const float* head1_b = (const float*)d_in[13];
    const float* head2_w = (const float*)d_in[14];
    const float* head2_b = (const float*)d_in[15];
    const float* thresh  = (const float*)d_in[16];
    const float* sharp   = (const float*)d_in[17];
    const float* scale   = (const float*)d_in[18];
    float* out = (float*)d_out;

    float*  f0;    cudaGetSymbolAddress((void**)&f0,    g_f0);
    float*  wcat1; cudaGetSymbolAddress((void**)&wcat1, g_wcat1);
    float*  bias1; cudaGetSymbolAddress((void**)&bias1, g_bias1);
    float*  c1;    cudaGetSymbolAddress((void**)&c1,    g_c1);
    float*  f1;    cudaGetSymbolAddress((void**)&f1,    g_f1);
    float*  wcat2; cudaGetSymbolAddress((void**)&wcat2, g_wcat2);
    float*  bias2; cudaGetSymbolAddress((void**)&bias2, g_bias2);
    float*  c2;    cudaGetSymbolAddress((void**)&c2,    g_c2);
    float*  f2;    cudaGetSymbolAddress((void**)&f2,    g_f2);
    float*  ghb;   cudaGetSymbolAddress((void**)&ghb,   g_ghb);
    float*  h;     cudaGetSymbolAddress((void**)&h,     g_h);

    // 1. prep (weight restructure + zero g0)
    prep1_kernel<<<(W0_ * W1_ + 255) / 256, 256>>>(b1_w, b1_b);
    prep2_kernel<<<(W1_ * W2_ + 255) / 256, 256>>>(b2_w, b2_b);
    // 2. stem + coords
    stem_kernel<<<PTS / 4, 256>>>(x, stem_w, stem_b, hmix_a, hmix_b, hmix_c);
    // 3. kNN: 4-way candidate-sliced scan + merge
    {
        dim3 grid(PTS / 128, SLICES);
        knn_part_kernel<<<grid, 128>>>();
        knn_merge_kernel<<<PTS / 128, 128>>>();
    }
    // 4. agg1 matvecs: c1 = f0 @ wcat1 (+bias1)
    {
        dim3 grid((2 * W1_) / 64, PTS / 128);
        gemm_kernel<<<grid, 256>>>(f0, wcat1, bias1, nullptr, c1, W0_, 2 * W1_, 0);
    }
    // 5. agg1 combine -> f1
    combine_kernel<<<PTS, W1_>>>(c1, b1_w + (2 * W0_) * W1_, f1, W1_);
    // 6. agg2 matvecs: c2 = f1 @ wcat2 (+bias2)
    {
        dim3 grid((2 * W2_) / 64, PTS / 128);
        gemm_kernel<<<grid, 256>>>(f1, wcat2, bias2, nullptr, c2, W1_, 2 * W2_, 0);
    }
    // 7. agg2 combine -> f2
    combine_kernel<<<PTS, W2_>>>(c2, b2_w + (2 * W1_) * W2_, f2, W2_);
    // 8. global max
    gmax_kernel<<<B_ * 32, 256>>>();
    // 9. per-batch glob MLP + g-part of head1 bias
    headg_kernel<<<B_, W2_>>>(glob_w, glob_b, head1_w, head1_b);
    // 10. head1: h = relu(f2 @ head1_w[0:256] + ghb[batch])
    {
        dim3 grid(W2_ / 64, PTS / 128);
        gemm_kernel<<<grid, 256>>>(f2, head1_w, nullptr, ghb, h, W2_, W2_, 1);
    }
    // 11. head2 + height bias
    head2_kernel<<<PTS / 4, 128>>>(head2_w, head2_b, x, thresh, sharp, scale, out);
}

// round 8
// speedup vs baseline: 1.2929x; 1.0749x over previous
#include <cuda_runtime.h>
#include <math.h>

// Problem constants
#define B_  4
#define N_  8192
#define PTS (B_ * N_)      // 32768
#define KNN 16
#define W0_ 64
#define W1_ 128
#define W2_ 256

#define QW   8              // queries (warps) per kNN block
#define KTILE 1024          // candidates per smem tile

// ---------------- scratch (static __device__ allowed) ----------------
__device__ float4 g_cxx [PTS];                // raw coords + xx (for combine dp)
__device__ float4 g_cxx2[PTS];                // (-2x, -2y, -2z, xx) for kNN metric
__device__ float  g_f0 [PTS * W0_];
__device__ int    g_idx[PTS * KNN];
__device__ float  g_wcat1[W0_ * (2 * W1_)];   // 64 x 256
__device__ float  g_bias1[2 * W1_];
__device__ float  g_c1 [PTS * (2 * W1_)];     // [t1 | s1]
__device__ float  g_f1 [PTS * W1_];
__device__ float  g_wcat2[W1_ * (2 * W2_)];   // 128 x 512
__device__ float  g_bias2[2 * W2_];
__device__ float  g_c2 [PTS * (2 * W2_)];     // [t2 | s2]
__device__ float  g_f2 [PTS * W2_];
__device__ unsigned int g_g0[B_ * W2_];       // global max (bits)
__device__ float  g_ghb[B_ * W2_];            // per-batch head1 bias row
__device__ float  g_h  [PTS * W2_];

// ---------------- f32x2 helpers ----------------
__device__ __forceinline__ unsigned long long pack_dup(float v) {
    unsigned long long r;
    asm("mov.b64 %0, {%1, %1};" : "=l"(r) : "r"(__float_as_uint(v)));
    return r;
}
__device__ __forceinline__ void fma2(unsigned long long& d, unsigned long long a,
                                     unsigned long long b) {
    asm("fma.rn.f32x2 %0, %1, %2, %0;" : "+l"(d) : "l"(a), "l"(b));
}
__device__ __forceinline__ void unpack2(unsigned long long v, float& lo, float& hi) {
    unsigned int l, h;
    asm("mov.b64 {%0, %1}, %2;" : "=r"(l), "=r"(h) : "l"(v));
    lo = __uint_as_float(l); hi = __uint_as_float(h);
}

// ---------------- prep kernels ----------------
__global__ void prep1_kernel(const float* __restrict__ b1w, const float* __restrict__ b1b) {
    int i = blockIdx.x * 256 + threadIdx.x;
    if (i < W0_ * W1_) {
        int d = i >> 7, o = i & 127;
        float wa = b1w[d * W1_ + o];
        float wb = b1w[(W0_ + d) * W1_ + o];
        g_wcat1[d * (2 * W1_) + o]        = wa - wb;
        g_wcat1[d * (2 * W1_) + W1_ + o]  = wb;
    }
    if (i < 2 * W1_) g_bias1[i] = (i < W1_) ? b1b[i] : 0.f;
}

__global__ void prep2_kernel(const float* __restrict__ b2w, const float* __restrict__ b2b) {
    int i = blockIdx.x * 256 + threadIdx.x;
    if (i < W1_ * W2_) {
        int d = i >> 8, o = i & 255;
        float wa = b2w[d * W2_ + o];
        float wb = b2w[(W1_ + d) * W2_ + o];
        g_wcat2[d * (2 * W2_) + o]        = wa - wb;
        g_wcat2[d * (2 * W2_) + W2_ + o]  = wb;
    }
    if (i < 2 * W2_) g_bias2[i] = (i < W2_) ? b2b[i] : 0.f;
    if (i < B_ * W2_) g_g0[i] = 0u;   // re-zero every call (deterministic)
}

// ---------------- stem: coords, xx, f0 ----------------
__global__ void stem_kernel(const float* __restrict__ x,
                            const float* __restrict__ sw, const float* __restrict__ sb,
                            const float* __restrict__ ha, const float* __restrict__ hb,
                            const float* __restrict__ hc) {
    __shared__ float xs[4][4];
    __shared__ float ws[4 * 64];
    __shared__ float bs[64];
    int tid = threadIdx.x;
    ws[tid] = sw[tid];                 // 256 == 4*64
    if (tid < 64) bs[tid] = sb[tid];
    int p = tid >> 6, o = tid & 63;
    int point = blockIdx.x * 4 + p;
    if (o < 4) xs[p][o] = x[point * 4 + o];
    __syncthreads();
    float acc = bs[o];
    #pragma unroll
    for (int i = 0; i < 4; i++) acc = fmaf(xs[p][i], ws[i * 64 + o], acc);
    g_f0[point * W0_ + o] = fmaxf(acc, 0.f);
    if (o == 0) {
        float x0 = xs[p][0], x1 = xs[p][1];
        float z = __fadd_rn(__fadd_rn(__fmul_rn(*ha, xs[p][2]), __fmul_rn(*hb, xs[p][3])), *hc);
        float xx = __fadd_rn(__fadd_rn(__fmul_rn(x0, x0), __fmul_rn(x1, x1)), __fmul_rn(z, z));
        g_cxx[point]  = make_float4(x0, x1, z, xx);
        g_cxx2[point] = make_float4(-2.f * x0, -2.f * x1, -2.f * z, xx);
    }
}

// ---------------- kNN: one query per warp, lane-distributed sorted top-16 ----------------
// Metric e = ||c||^2 - 2 q.c  (query-constant shift of true sq-dist; same ordering).
// Admission: strict e < thr (thr = current 16th value, lane 15). Inserts are
// warp-uniform shuffle shifts; ties keep earlier (lower-index) candidates.
__global__ __launch_bounds__(QW * 32) void knn_kernel() {
    __shared__ float4 tile[KTILE];
    const unsigned FULL = 0xffffffffu;
    int warp = threadIdx.x >> 5, lane = threadIdx.x & 31;
    int q = blockIdx.x * QW + warp;
    int base = (q >> 13) << 13;        // batch start
    float4 cq = g_cxx[q];              // (x, y, z, xx) - raw coords
    float lv = 3.4e38f;                // lanes 0..15: sorted ascending list values
    int   li = 0;
    float thr = 3.4e38f;

    for (int t0 = 0; t0 < N_; t0 += KTILE) {
        __syncthreads();
        #pragma unroll
        for (int i = 0; i < KTILE / (QW * 32); i++)
            tile[threadIdx.x + i * (QW * 32)] = g_cxx2[base + t0 + threadIdx.x + i * (QW * 32)];
        __syncthreads();
        #pragma unroll 2
        for (int j0 = 0; j0 < KTILE; j0 += 32) {
            float4 cm = tile[j0 + lane];
            float e = fmaf(cm.x, cq.x, fmaf(cm.y, cq.y, fmaf(cm.z, cq.z, cm.w)));
            unsigned m = __ballot_sync(FULL, e < thr);
            while (m) {                        // warp-uniform loop
                int src = __ffs(m) - 1;
                m &= m - 1;
                float ev = __shfl_sync(FULL, e, src);
                if (ev < thr) {                // recheck vs tightened thr (uniform)
                    int ei = base + t0 + j0 + src;
                    // keep: element stays at its lane (insert after equals)
                    bool keep = (lv <= ev);
                    unsigned bm = __ballot_sync(FULL, keep);
                    bm = (bm << 1) | 1u;       // predecessor-keeps, lane0 -> true
                    bool upkeep = (bm >> lane) & 1u;
                    float upv = __shfl_up_sync(FULL, lv, 1);
                    int   upi = __shfl_up_sync(FULL, li, 1);
                    lv = keep ? lv : (upkeep ? ev : upv);
                    li = keep ? li : (upkeep ? ei : upi);
                    thr = __shfl_sync(FULL, lv, 15);
                }
            }
        }
    }
    if (lane < KNN) g_idx[q * KNN + lane] = li;
}

// ---------------- tiled GEMM with f32x2 packed FMA ----------------
// C[M,N] = A[M,K] @ W[K,N] (+bias, +rowbias, relu). BM=128, BN=64, BK=16,
// 256 threads, 8x4 per thread, accumulator packed pairwise along M.
__global__ __launch_bounds__(256) void gemm_kernel(
        const float* __restrict__ A, const float* __restrict__ W,
        const float* __restrict__ bias, const float* __restrict__ rowbias,
        float* __restrict__ C, int K, int N, int do_relu) {
    const int BM = 128, BN = 64, BK = 16;
    __shared__ float As[BK][BM];
    __shared__ float Ws[BK][BN];
    int tid = threadIdx.x;
    int tx = tid & 15, ty = tid >> 4;
    int rowTile = blockIdx.y * BM;
    int colTile = blockIdx.x * BN;
    unsigned long long acc2[4][4];     // [i-pair][j], lo = row 2*i2, hi = row 2*i2+1
    #pragma unroll
    for (int i = 0; i < 4; i++)
        #pragma unroll
        for (int j = 0; j < 4; j++) acc2[i][j] = 0ull;

    for (int k0 = 0; k0 < K; k0 += BK) {
        {   // A tile: 128 rows x 16 k, thread loads 8 (two float4), store transposed
            int r  = tid >> 1;
            int kk = (tid & 1) * 8;
            const float* src = A + (size_t)(rowTile + r) * K + k0 + kk;
            float4 v0 = *(const float4*)(src);
            float4 v1 = *(const float4*)(src + 4);
            As[kk + 0][r] = v0.x; As[kk + 1][r] = v0.y; As[kk + 2][r] = v0.z; As[kk + 3][r] = v0.w;
            As[kk + 4][r] = v1.x; As[kk + 5][r] = v1.y; As[kk + 6][r] = v1.z; As[kk + 7][r] = v1.w;
        }
        {   // W tile: 16 x 64, thread loads 4
            int kw = tid >> 4;
            int c  = (tid & 15) * 4;
            float4 v = *(const float4*)(W + (size_t)(k0 + kw) * N + colTile + c);
            Ws[kw][c] = v.x; Ws[kw][c + 1] = v.y; Ws[kw][c + 2] = v.z; Ws[kw][c + 3] = v.w;
        }
        __syncthreads();
        #pragma unroll
        for (int kk = 0; kk < BK; kk++) {
            unsigned long long a2[4];
            #pragma unroll
            for (int i2 = 0; i2 < 4; i2++)
                a2[i2] = *(const unsigned long long*)&As[kk][ty * 8 + i2 * 2];
            #pragma unroll
            for (int j = 0; j < 4; j++) {
                unsigned long long b2 = pack_dup(Ws[kk][tx * 4 + j]);
                #pragma unroll
                for (int i2 = 0; i2 < 4; i2++) fma2(acc2[i2][j], a2[i2], b2);
            }
        }
        __syncthreads();
    }

    int batchoff = (rowTile >> 13) * N;   // batch constant per 128-row tile
    float bv[4];
    #pragma unroll
    for (int j = 0; j < 4; j++) {
        int col = colTile + tx * 4 + j;
        float v = bias ? bias[col] : 0.f;
        if (rowbias) v += rowbias[batchoff + col];
        bv[j] = v;
    }
    #pragma unroll
    for (int i2 = 0; i2 < 4; i2++) {
        float lo[4], hi[4];
        #pragma unroll
        for (int j = 0; j < 4; j++) {
            unpack2(acc2[i2][j], lo[j], hi[j]);
            lo[j] += bv[j]; hi[j] += bv[j];
            if (do_relu) { lo[j] = fmaxf(lo[j], 0.f); hi[j] = fmaxf(hi[j], 0.f); }
        }
        int r0 = rowTile + ty * 8 + i2 * 2;
        float4 o0 = make_float4(lo[0], lo[1], lo[2], lo[3]);
        float4 o1 = make_float4(hi[0], hi[1], hi[2], hi[3]);
        *(float4*)(C + (size_t)r0 * N + colTile + tx * 4) = o0;
        *(float4*)(C + (size_t)(r0 + 1) * N + colTile + tx * 4) = o1;
    }
}

// ---------------- combine: out[n][o] = max_k relu(t[n][o] + s[idx][o] + dp . wc[:,o]) ----------------
__global__ void combine_kernel(const float* __restrict__ C, const float* __restrict__ wc,
                               float* __restrict__ out, int F) {
    int n = blockIdx.x;
    int o = threadIdx.x;
    __shared__ int   sidx[KNN];
    __shared__ float sdp[KNN][3];
    if (o < KNN) {
        int m = g_idx[n * KNN + o];
        sidx[o] = m;
        float4 cm = g_cxx[m];
        float4 cn = g_cxx[n];
        sdp[o][0] = cm.x - cn.x; sdp[o][1] = cm.y - cn.y; sdp[o][2] = cm.z - cn.z;
    }
    __syncthreads();
    int twoF = 2 * F;
    float tv = C[(size_t)n * twoF + o];
    float w0 = wc[o], w1 = wc[F + o], w2 = wc[2 * F + o];
    float best = 0.f;
    #pragma unroll 4
    for (int k = 0; k < KNN; k++) {
        int m = sidx[k];
        float sv = C[(size_t)m * twoF + F + o];
        float v = tv + sv;
        v = fmaf(sdp[k][0], w0, v);
        v = fmaf(sdp[k][1], w1, v);
        v = fmaf(sdp[k][2], w2, v);
        best = fmaxf(best, v);
    }
    out[(size_t)n * F + o] = best;
}

// ---------------- global max over points ----------------
__global__ void gmax_kernel() {
    int b  = blockIdx.x >> 5;
    int sp = blockIdx.x & 31;
    int o  = threadIdx.x;
    float m = 0.f;
    int n0 = b * N_ + sp * 256;
    for (int i = 0; i < 256; i++) m = fmaxf(m, g_f2[(size_t)(n0 + i) * W2_ + o]);
    atomicMax(&g_g0[b * W2_ + o], __float_as_uint(m));   // f2 >= 0
}

// ---------------- per-batch global MLP + head1 g-bias ----------------
__global__ void headg_kernel(const float* __restrict__ gw, const float* __restrict__ gb,
                             const float* __restrict__ h1w, const float* __restrict__ h1b) {
    int b = blockIdx.x;
    int o = threadIdx.x;
    __shared__ float s0[W2_], s1[W2_];
    s0[o] = __uint_as_float(g_g0[b * W2_ + o]);
    __syncthreads();
    float acc = gb[o];
    for (int d = 0; d < W2_; d++) acc = fmaf(s0[d], gw[d * W2_ + o], acc);
    s1[o] = fmaxf(acc, 0.f);
    __syncthreads();
    float acc2 = h1b[o];
    for (int d = 0; d < W2_; d++) acc2 = fmaf(s1[d], h1w[(W2_ + d) * W2_ + o], acc2);
    g_ghb[b * W2_ + o] = acc2;
}

// ---------------- head2 + height bias ----------------
__global__ __launch_bounds__(128) void head2_kernel(const float* __restrict__ w2, const float* __restrict__ b2,
                                                    const float* __restrict__ x,
                                                    const float* __restrict__ thresh, const float* __restrict__ sharp,
                                                    const float* __restrict__ scale, float* __restrict__ out) {
    int warp = threadIdx.x >> 5, lane = threadIdx.x & 31;
    int n = blockIdx.x * 4 + warp;
    float a0 = 0.f, a1 = 0.f, a2 = 0.f;
    #pragma unroll
    for (int i = 0; i < 8; i++) {
        int d = lane + i * 32;
        float hv = g_h[(size_t)n * W2_ + d];
        a0 = fmaf(hv, w2[d * 3 + 0], a0);
        a1 = fmaf(hv, w2[d * 3 + 1], a1);
        a2 = fmaf(hv, w2[d * 3 + 2], a2);
    }
    #pragma unroll
    for (int off = 16; off; off >>= 1) {
        a0 += __shfl_down_sync(0xffffffffu, a0, off);
        a1 += __shfl_down_sync(0xffffffffu, a1, off);
        a2 += __shfl_down_sync(0xffffffffu, a2, off);
    }
    if (lane == 0) {
        float hag = x[n * 4 + 3];
        float hb = (*scale) / (1.f + expf((*sharp) * (hag - (*thresh))));
        out[n * 3 + 0] = a0 + b2[0] + hb;
        out[n * 3 + 1] = a1 + b2[1];
        out[n * 3 + 2] = a2 + b2[2];
    }
}

// ---------------- launcher ----------------
extern "C" void kernel_launch(void* const* d_in, const int* in_sizes, int n_in,
                              void* d_out, int out_size) {
    const float* x       = (const float*)d_in[0];
    const float* hmix_a  = (const float*)d_in[1];
    const float* hmix_b  = (const float*)d_in[2];
    const float* hmix_c  = (const float*)d_in[3];
    const float* stem_w  = (const float*)d_in[4];
    const float* stem_b  = (const float*)d_in[5];
    const float* b1_w    = (const float*)d_in[6];
    const float* b1_b    = (const float*)d_in[7];
    const float* b2_w    = (const float*)d_in[8];
    const float* b2_b    = (const float*)d_in[9];
    const float* glob_w  = (const float*)d_in[10];
    const float* glob_b  = (const float*)d_in[11];
    const float* head1_w = (const float*)d_in[12];
    const float* head1_b = (const float*)d_in[13];
    const float* head2_w = (const float*)d_in[14];
    const float* head2_b = (const float*)d_in[15];
    const float* thresh  = (const float*)d_in[16];
    const float* sharp   = (const float*)d_in[17];
    const float* scale   = (const float*)d_in[18];
    float* out = (float*)d_out;

    float*  f0;    cudaGetSymbolAddress((void**)&f0,    g_f0);
    float*  wcat1; cudaGetSymbolAddress((void**)&wcat1, g_wcat1);
    float*  bias1; cudaGetSymbolAddress((void**)&bias1, g_bias1);
    float*  c1;    cudaGetSymbolAddress((void**)&c1,    g_c1);
    float*  f1;    cudaGetSymbolAddress((void**)&f1,    g_f1);
    float*  wcat2; cudaGetSymbolAddress((void**)&wcat2, g_wcat2);
    float*  bias2; cudaGetSymbolAddress((void**)&bias2, g_bias2);
    float*  c2;    cudaGetSymbolAddress((void**)&c2,    g_c2);
    float*  f2;    cudaGetSymbolAddress((void**)&f2,    g_f2);
    float*  ghb;   cudaGetSymbolAddress((void**)&ghb,   g_ghb);
    float*  h;     cudaGetSymbolAddress((void**)&h,     g_h);

    // 1. prep (weight restructure + zero g0)
    prep1_kernel<<<(W0_ * W1_ + 255) / 256, 256>>>(b1_w, b1_b);
    prep2_kernel<<<(W1_ * W2_ + 255) / 256, 256>>>(b2_w, b2_b);
    // 2. stem + coords (raw + kNN-metric coords)
    stem_kernel<<<PTS / 4, 256>>>(x, stem_w, stem_b, hmix_a, hmix_b, hmix_c);
    // 3. kNN: one query per warp, warp-cooperative top-16
    knn_kernel<<<PTS / QW, QW * 32>>>();
    // 4. agg1 matvecs: c1 = f0 @ wcat1 (+bias1)
    {
        dim3 grid((2 * W1_) / 64, PTS / 128);
        gemm_kernel<<<grid, 256>>>(f0, wcat1, bias1, nullptr, c1, W0_, 2 * W1_, 0);
    }
    // 5. agg1 combine -> f1
    combine_kernel<<<PTS, W1_>>>(c1, b1_w + (2 * W0_) * W1_, f1, W1_);
    // 6. agg2 matvecs: c2 = f1 @ wcat2 (+bias2)
    {
        dim3 grid((2 * W2_) / 64, PTS / 128);
        gemm_kernel<<<grid, 256>>>(f1, wcat2, bias2, nullptr, c2, W1_, 2 * W2_, 0);
    }
    // 7. agg2 combine -> f2
    combine_kernel<<<PTS, W2_>>>(c2, b2_w + (2 * W1_) * W2_, f2, W2_);
    // 8. global max
    gmax_kernel<<<B_ * 32, 256>>>();
    // 9. per-batch glob MLP + g-part of head1 bias
    headg_kernel<<<B_, W2_>>>(glob_w, glob_b, head1_w, head1_b);
    // 10. head1: h = relu(f2 @ head1_w[0:256] + ghb[batch])
    {
        dim3 grid(W2_ / 64, PTS / 128);
        gemm_kernel<<<grid, 256>>>(f2, head1_w, nullptr, ghb, h, W2_, W2_, 1);
    }
    // 11. head2 + height bias
    head2_kernel<<<PTS / 4, 128>>>(head2_w, head2_b, x, thresh, sharp, scale, out);
}

// round 9
// speedup vs baseline: 2.0813x; 1.6099x over previous
#include <cuda_runtime.h>
#include <math.h>

// Problem constants
#define B_  4
#define N_  8192
#define PTS (B_ * N_)      // 32768
#define KNN 16
#define W0_ 64
#define W1_ 128
#define W2_ 256

#define QW   8              // warps per kNN block (each warp = 2 queries)
#define KTILE 1024          // candidates per smem tile

// ---------------- scratch (static __device__ allowed) ----------------
__device__ float4 g_cxx [PTS];                // raw coords + xx (for combine dp)
__device__ float4 g_cxx2[PTS];                // (-2x, -2y, -2z, xx) for kNN metric
__device__ float  g_f0 [PTS * W0_];
__device__ int    g_idx[PTS * KNN];
__device__ float  g_wcat1[W0_ * (2 * W1_)];   // 64 x 256
__device__ float  g_bias1[2 * W1_];
__device__ float  g_c1 [PTS * (2 * W1_)];     // [t1 | s1]
__device__ float  g_f1 [PTS * W1_];
__device__ float  g_wcat2[W1_ * (2 * W2_)];   // 128 x 512
__device__ float  g_bias2[2 * W2_];
__device__ float  g_c2 [PTS * (2 * W2_)];     // [t2 | s2]
__device__ float  g_f2 [PTS * W2_];
__device__ unsigned int g_g0[B_ * W2_];       // global max (bits)
__device__ float  g_ghb[B_ * W2_];            // per-batch head1 bias row
__device__ float  g_h  [PTS * W2_];

// ---------------- f32x2 helpers ----------------
__device__ __forceinline__ unsigned long long pack_dup(float v) {
    unsigned long long r;
    asm("mov.b64 %0, {%1, %1};" : "=l"(r) : "r"(__float_as_uint(v)));
    return r;
}
__device__ __forceinline__ void fma2(unsigned long long& d, unsigned long long a,
                                     unsigned long long b) {
    asm("fma.rn.f32x2 %0, %1, %2, %0;" : "+l"(d) : "l"(a), "l"(b));
}
__device__ __forceinline__ void unpack2(unsigned long long v, float& lo, float& hi) {
    unsigned int l, h;
    asm("mov.b64 {%0, %1}, %2;" : "=r"(l), "=r"(h) : "l"(v));
    lo = __uint_as_float(l); hi = __uint_as_float(h);
}

// ---------------- prep kernels ----------------
__global__ void prep1_kernel(const float* __restrict__ b1w, const float* __restrict__ b1b) {
    int i = blockIdx.x * 256 + threadIdx.x;
    if (i < W0_ * W1_) {
        int d = i >> 7, o = i & 127;
        float wa = b1w[d * W1_ + o];
        float wb = b1w[(W0_ + d) * W1_ + o];
        g_wcat1[d * (2 * W1_) + o]        = wa - wb;
        g_wcat1[d * (2 * W1_) + W1_ + o]  = wb;
    }
    if (i < 2 * W1_) g_bias1[i] = (i < W1_) ? b1b[i] : 0.f;
}

__global__ void prep2_kernel(const float* __restrict__ b2w, const float* __restrict__ b2b) {
    int i = blockIdx.x * 256 + threadIdx.x;
    if (i < W1_ * W2_) {
        int d = i >> 8, o = i & 255;
        float wa = b2w[d * W2_ + o];
        float wb = b2w[(W1_ + d) * W2_ + o];
        g_wcat2[d * (2 * W2_) + o]        = wa - wb;
        g_wcat2[d * (2 * W2_) + W2_ + o]  = wb;
    }
    if (i < 2 * W2_) g_bias2[i] = (i < W2_) ? b2b[i] : 0.f;
    if (i < B_ * W2_) g_g0[i] = 0u;   // re-zero every call (deterministic)
}

// ---------------- stem: coords, xx, f0 ----------------
__global__ void stem_kernel(const float* __restrict__ x,
                            const float* __restrict__ sw, const float* __restrict__ sb,
                            const float* __restrict__ ha, const float* __restrict__ hb,
                            const float* __restrict__ hc) {
    __shared__ float xs[4][4];
    __shared__ float ws[4 * 64];
    __shared__ float bs[64];
    int tid = threadIdx.x;
    ws[tid] = sw[tid];                 // 256 == 4*64
    if (tid < 64) bs[tid] = sb[tid];
    int p = tid >> 6, o = tid & 63;
    int point = blockIdx.x * 4 + p;
    if (o < 4) xs[p][o] = x[point * 4 + o];
    __syncthreads();
    float acc = bs[o];
    #pragma unroll
    for (int i = 0; i < 4; i++) acc = fmaf(xs[p][i], ws[i * 64 + o], acc);
    g_f0[point * W0_ + o] = fmaxf(acc, 0.f);
    if (o == 0) {
        float x0 = xs[p][0], x1 = xs[p][1];
        float z = __fadd_rn(__fadd_rn(__fmul_rn(*ha, xs[p][2]), __fmul_rn(*hb, xs[p][3])), *hc);
        float xx = __fadd_rn(__fadd_rn(__fmul_rn(x0, x0), __fmul_rn(x1, x1)), __fmul_rn(z, z));
        g_cxx[point]  = make_float4(x0, x1, z, xx);
        g_cxx2[point] = make_float4(-2.f * x0, -2.f * x1, -2.f * z, xx);
    }
}

// ---------------- kNN: TWO queries per warp, segmented lane-distributed top-16 ----------------
// Metric e = ||c||^2 - 2 q.c (query-constant shift of true sq-dist; same ordering).
// List A sorted ascending in lanes 0..15 of lv; list B in lanes 16..31.
// Inserts are segmented shuffle shifts (width-16 semantics via the bm mask trick):
// bm = (keep-ballot << 1) | 0x00010001 pins both segment heads to "predecessor keeps";
// a segment head never consumes shfl_up cross-segment data (upkeep=1 there).
// Ties keep earlier (lower-index) candidates: ffs ascending + strict < + insert-after-equals.
__global__ __launch_bounds__(QW * 32) void knn_kernel() {
    __shared__ float4 tile[KTILE];
    const unsigned FULL = 0xffffffffu;
    int warp = threadIdx.x >> 5, lane = threadIdx.x & 31;
    int seg = lane >> 4, segLane = lane & 15;
    int q2 = blockIdx.x * QW + warp;          // query pair
    int qA = q2 * 2, qB = qA + 1;             // same batch (8192 even)
    int base = (qA >> 13) << 13;
    float4 ca = g_cxx[qA];
    float4 cb = g_cxx[qB];
    float lv = 3.4e38f;                       // my segment's sorted list value
    int   li = 0;
    float thrA = 3.4e38f, thrB = 3.4e38f;

    for (int t0 = 0; t0 < N_; t0 += KTILE) {
        __syncthreads();
        #pragma unroll
        for (int i = 0; i < KTILE / (QW * 32); i++)
            tile[threadIdx.x + i * (QW * 32)] = g_cxx2[base + t0 + threadIdx.x + i * (QW * 32)];
        __syncthreads();
        #pragma unroll 2
        for (int j0 = 0; j0 < KTILE; j0 += 32) {
            float4 cm = tile[j0 + lane];
            float eA = fmaf(cm.x, ca.x, fmaf(cm.y, ca.y, fmaf(cm.z, ca.z, cm.w)));
            float eB = fmaf(cm.x, cb.x, fmaf(cm.y, cb.y, fmaf(cm.z, cb.z, cm.w)));
            unsigned mA = __ballot_sync(FULL, eA < thrA);
            unsigned mB = __ballot_sync(FULL, eB < thrB);
            while (mA | mB) {                 // warp-uniform loop
                bool hadA = (mA != 0), hadB = (mB != 0);
                int srcA = hadA ? (__ffs(mA) - 1) : 0;
                int srcB = hadB ? (__ffs(mB) - 1) : 0;
                mA &= mA - 1;                 // pop (0-safe)
                mB &= mB - 1;
                float evA = __shfl_sync(FULL, eA, srcA);
                float evB = __shfl_sync(FULL, eB, srcB);
                bool insA = hadA && (evA < thrA);   // recheck vs tightened thr (uniform)
                bool insB = hadB && (evB < thrB);
                if (insA | insB) {
                    float cv   = seg ? evB : evA;
                    int   ci   = base + t0 + j0 + (seg ? srcB : srcA);
                    bool doIns = seg ? insB : insA;      // segment-uniform
                    bool keep  = !doIns || (lv <= cv);   // insert after equals
                    unsigned bm = __ballot_sync(FULL, keep);
                    bm = (bm << 1) | 0x00010001u;        // pin both segment heads
                    bool upkeep = (bm >> lane) & 1u;
                    float upv = __shfl_up_sync(FULL, lv, 1);
                    int   upi = __shfl_up_sync(FULL, li, 1);
                    lv = keep ? lv : (upkeep ? cv : upv);
                    li = keep ? li : (upkeep ? ci : upi);
                    thrA = __shfl_sync(FULL, lv, 15);
                    thrB = __shfl_sync(FULL, lv, 31);
                }
            }
        }
    }
    int q = seg ? qB : qA;
    g_idx[q * KNN + segLane] = li;
}

// ---------------- tiled GEMM, f32x2 packed FMA, 2-stage double buffer ----------------
// C[M,N] = A[M,K] @ W[K,N] (+bias, +rowbias, relu). BM=128, BN=64, BK=16,
// 256 threads, 8x4 per thread, one __syncthreads per k-tile, LDG overlapped.
__global__ __launch_bounds__(256) void gemm_kernel(
        const float* __restrict__ A, const float* __restrict__ W,
        const float* __restrict__ bias, const float* __restrict__ rowbias,
        float* __restrict__ C, int K, int N, int do_relu) {
    const int BM = 128, BN = 64, BK = 16;
    __shared__ float As[2][BK][BM];
    __shared__ float Ws[2][BK][BN];
    int tid = threadIdx.x;
    int tx = tid & 15, ty = tid >> 4;
    int rowTile = blockIdx.y * BM;
    int colTile = blockIdx.x * BN;
    int r   = tid >> 1,  kk8 = (tid & 1) * 8;     // A-load mapping
    int kw  = tid >> 4,  cc  = (tid & 15) * 4;    // W-load mapping
    const float* aSrc = A + (size_t)(rowTile + r) * K + kk8;
    const float* wSrc = W + (size_t)kw * N + colTile + cc;

    unsigned long long acc2[4][4];
    #pragma unroll
    for (int i = 0; i < 4; i++)
        #pragma unroll
        for (int j = 0; j < 4; j++) acc2[i][j] = 0ull;

    int ntiles = K / BK;
    float4 a0 = *(const float4*)(aSrc);
    float4 a1 = *(const float4*)(aSrc + 4);
    float4 wv = *(const float4*)(wSrc);
    {   // stage tile 0
        As[0][kk8 + 0][r] = a0.x; As[0][kk8 + 1][r] = a0.y; As[0][kk8 + 2][r] = a0.z; As[0][kk8 + 3][r] = a0.w;
        As[0][kk8 + 4][r] = a1.x; As[0][kk8 + 5][r] = a1.y; As[0][kk8 + 6][r] = a1.z; As[0][kk8 + 7][r] = a1.w;
        Ws[0][kw][cc] = wv.x; Ws[0][kw][cc + 1] = wv.y; Ws[0][kw][cc + 2] = wv.z; Ws[0][kw][cc + 3] = wv.w;
    }
    __syncthreads();

    for (int t = 0; t < ntiles; t++) {
        int cur = t & 1;
        if (t + 1 < ntiles) {                     // prefetch next tile
            a0 = *(const float4*)(aSrc + (t + 1) * BK);
            a1 = *(const float4*)(aSrc + (t + 1) * BK + 4);
            wv = *(const float4*)(wSrc + (size_t)(t + 1) * BK * N);
        }
        #pragma unroll
        for (int kk = 0; kk < BK; kk++) {
            unsigned long long a2[4];
            #pragma unroll
            for (int i2 = 0; i2 < 4; i2++)
                a2[i2] = *(const unsigned long long*)&As[cur][kk][ty * 8 + i2 * 2];
            #pragma unroll
            for (int j = 0; j < 4; j++) {
                unsigned long long b2 = pack_dup(Ws[cur][kk][tx * 4 + j]);
                #pragma unroll
                for (int i2 = 0; i2 < 4; i2++) fma2(acc2[i2][j], a2[i2], b2);
            }
        }
        if (t + 1 < ntiles) {                     // stage next tile (buf freed by last sync)
            int nxt = cur ^ 1;
            As[nxt][kk8 + 0][r] = a0.x; As[nxt][kk8 + 1][r] = a0.y; As[nxt][kk8 + 2][r] = a0.z; As[nxt][kk8 + 3][r] = a0.w;
            As[nxt][kk8 + 4][r] = a1.x; As[nxt][kk8 + 5][r] = a1.y; As[nxt][kk8 + 6][r] = a1.z; As[nxt][kk8 + 7][r] = a1.w;
            Ws[nxt][kw][cc] = wv.x; Ws[nxt][kw][cc + 1] = wv.y; Ws[nxt][kw][cc + 2] = wv.z; Ws[nxt][kw][cc + 3] = wv.w;
        }
        __syncthreads();
    }

    int batchoff = (rowTile >> 13) * N;   // batch constant per 128-row tile
    float bv[4];
    #pragma unroll
    for (int j = 0; j < 4; j++) {
        int col = colTile + tx * 4 + j;
        float v = bias ? bias[col] : 0.f;
        if (rowbias) v += rowbias[batchoff + col];
        bv[j] = v;
    }
    #pragma unroll
    for (int i2 = 0; i2 < 4; i2++) {
        float lo[4], hi[4];
        #pragma unroll
        for (int j = 0; j < 4; j++) {
            unpack2(acc2[i2][j], lo[j], hi[j]);
            lo[j] += bv[j]; hi[j] += bv[j];
            if (do_relu) { lo[j] = fmaxf(lo[j], 0.f); hi[j] = fmaxf(hi[j], 0.f); }
        }
        int r0 = rowTile + ty * 8 + i2 * 2;
        float4 o0 = make_float4(lo[0], lo[1], lo[2], lo[3]);
        float4 o1 = make_float4(hi[0], hi[1], hi[2], hi[3]);
        *(float4*)(C + (size_t)r0 * N + colTile + tx * 4) = o0;
        *(float4*)(C + (size_t)(r0 + 1) * N + colTile + tx * 4) = o1;
    }
}

// ---------------- combine: out[n][o] = max_k relu(t[n][o] + s[idx][o] + dp . wc[:,o]) ----------------
__global__ void combine_kernel(const float* __restrict__ C, const float* __restrict__ wc,
                               float* __restrict__ out, int F) {
    int n = blockIdx.x;
    int o = threadIdx.x;
    __shared__ int   sidx[KNN];
    __shared__ float sdp[KNN][3];
    if (o < KNN) {
        int m = g_idx[n * KNN + o];
        sidx[o] = m;
        float4 cm = g_cxx[m];
        float4 cn = g_cxx[n];
        sdp[o][0] = cm.x - cn.x; sdp[o][1] = cm.y - cn.y; sdp[o][2] = cm.z - cn.z;
    }
    __syncthreads();
    int twoF = 2 * F;
    float tv = C[(size_t)n * twoF + o];
    float w0 = wc[o], w1 = wc[F + o], w2 = wc[2 * F + o];
    float best = 0.f;
    #pragma unroll 4
    for (int k = 0; k < KNN; k++) {
        int m = sidx[k];
        float sv = C[(size_t)m * twoF + F + o];
        float v = tv + sv;
        v = fmaf(sdp[k][0], w0, v);
        v = fmaf(sdp[k][1], w1, v);
        v = fmaf(sdp[k][2], w2, v);
        best = fmaxf(best, v);
    }
    out[(size_t)n * F + o] = best;
}

// ---------------- global max over points ----------------
__global__ void gmax_kernel() {
    int b  = blockIdx.x >> 5;
    int sp = blockIdx.x & 31;
    int o  = threadIdx.x;
    float m = 0.f;
    int n0 = b * N_ + sp * 256;
    for (int i = 0; i < 256; i++) m = fmaxf(m, g_f2[(size_t)(n0 + i) * W2_ + o]);
    atomicMax(&g_g0[b * W2_ + o], __float_as_uint(m));   // f2 >= 0
}

// ---------------- per-batch global MLP + head1 g-bias ----------------
__global__ void headg_kernel(const float* __restrict__ gw, const float* __restrict__ gb,
                             const float* __restrict__ h1w, const float* __restrict__ h1b) {
    int b = blockIdx.x;
    int o = threadIdx.x;
    __shared__ float s0[W2_], s1[W2_];
    s0[o] = __uint_as_float(g_g0[b * W2_ + o]);
    __syncthreads();
    float acc = gb[o];
    for (int d = 0; d < W2_; d++) acc = fmaf(s0[d], gw[d * W2_ + o], acc);
    s1[o] = fmaxf(acc, 0.f);
    __syncthreads();
    float acc2 = h1b[o];
    for (int d = 0; d < W2_; d++) acc2 = fmaf(s1[d], h1w[(W2_ + d) * W2_ + o], acc2);
    g_ghb[b * W2_ + o] = acc2;
}

// ---------------- head2 + height bias ----------------
__global__ __launch_bounds__(128) void head2_kernel(const float* __restrict__ w2, const float* __restrict__ b2,
                                                    const float* __restrict__ x,
                                                    const float* __restrict__ thresh, const float* __restrict__ sharp,
                                                    const float* __restrict__ scale, float* __restrict__ out) {
    int warp = threadIdx.x >> 5, lane = threadIdx.x & 31;
    int n = blockIdx.x * 4 + warp;
    float a0 = 0.f, a1 = 0.f, a2 = 0.f;
    #pragma unroll
    for (int i = 0; i < 8; i++) {
        int d = lane + i * 32;
        float hv = g_h[(size_t)n * W2_ + d];
        a0 = fmaf(hv, w2[d * 3 + 0], a0);
        a1 = fmaf(hv, w2[d * 3 + 1], a1);
        a2 = fmaf(hv, w2[d * 3 + 2], a2);
    }
    #pragma unroll
    for (int off = 16; off; off >>= 1) {
        a0 += __shfl_down_sync(0xffffffffu, a0, off);
        a1 += __shfl_down_sync(0xffffffffu, a1, off);
        a2 += __shfl_down_sync(0xffffffffu, a2, off);
    }
    if (lane == 0) {
        float hag = x[n * 4 + 3];
        float hb = (*scale) / (1.f + expf((*sharp) * (hag - (*thresh))));
        out[n * 3 + 0] = a0 + b2[0] + hb;
        out[n * 3 + 1] = a1 + b2[1];
        out[n * 3 + 2] = a2 + b2[2];
    }
}

// ---------------- launcher ----------------
extern "C" void kernel_launch(void* const* d_in, const int* in_sizes, int n_in,
                              void* d_out, int out_size) {
    const float* x       = (const float*)d_in[0];
    const float* hmix_a  = (const float*)d_in[1];
    const float* hmix_b  = (const float*)d_in[2];
    const float* hmix_c  = (const float*)d_in[3];
    const float* stem_w  = (const float*)d_in[4];
    const float* stem_b  = (const float*)d_in[5];
    const float* b1_w    = (const float*)d_in[6];
    const float* b1_b    = (const float*)d_in[7];
    const float* b2_w    = (const float*)d_in[8];
    const float* b2_b    = (const float*)d_in[9];
    const float* glob_w  = (const float*)d_in[10];
    const float* glob_b  = (const float*)d_in[11];
    const float* head1_w = (const float*)d_in[12];
    const float* head1_b = (const float*)d_in[13];
    const float* head2_w = (const float*)d_in[14];
    const float* head2_b = (const float*)d_in[15];
    const float* thresh  = (const float*)d_in[16];
    const float* sharp   = (const float*)d_in[17];
    const float* scale   = (const float*)d_in[18];
    float* out = (float*)d_out;

    float*  f0;    cudaGetSymbolAddress((void**)&f0,    g_f0);
    float*  wcat1; cudaGetSymbolAddress((void**)&wcat1, g_wcat1);
    float*  bias1; cudaGetSymbolAddress((void**)&bias1, g_bias1);
    float*  c1;    cudaGetSymbolAddress((void**)&c1,    g_c1);
    float*  f1;    cudaGetSymbolAddress((void**)&f1,    g_f1);
    float*  wcat2; cudaGetSymbolAddress((void**)&wcat2, g_wcat2);
    float*  bias2; cudaGetSymbolAddress((void**)&bias2, g_bias2);
    float*  c2;    cudaGetSymbolAddress((void**)&c2,    g_c2);
    float*  f2;    cudaGetSymbolAddress((void**)&f2,    g_f2);
    float*  ghb;   cudaGetSymbolAddress((void**)&ghb,   g_ghb);
    float*  h;     cudaGetSymbolAddress((void**)&h,     g_h);

    // 1. prep (weight restructure + zero g0)
    prep1_kernel<<<(W0_ * W1_ + 255) / 256, 256>>>(b1_w, b1_b);
    prep2_kernel<<<(W1_ * W2_ + 255) / 256, 256>>>(b2_w, b2_b);
    // 2. stem + coords (raw + kNN-metric coords)
    stem_kernel<<<PTS / 4, 256>>>(x, stem_w, stem_b, hmix_a, hmix_b, hmix_c);
    // 3. kNN: two queries per warp, segmented warp-cooperative top-16
    knn_kernel<<<PTS / (2 * QW), QW * 32>>>();
    // 4. agg1 matvecs: c1 = f0 @ wcat1 (+bias1)
    {
        dim3 grid((2 * W1_) / 64, PTS / 128);
        gemm_kernel<<<grid, 256>>>(f0, wcat1, bias1, nullptr, c1, W0_, 2 * W1_, 0);
    }
    // 5. agg1 combine -> f1
    combine_kernel<<<PTS, W1_>>>(c1, b1_w + (2 * W0_) * W1_, f1, W1_);
    // 6. agg2 matvecs: c2 = f1 @ wcat2 (+bias2)
    {
        dim3 grid((2 * W2_) / 64, PTS / 128);
        gemm_kernel<<<grid, 256>>>(f1, wcat2, bias2, nullptr, c2, W1_, 2 * W2_, 0);
    }
    // 7. agg2 combine -> f2
    combine_kernel<<<PTS, W2_>>>(c2, b2_w + (2 * W1_) * W2_, f2, W2_);
    // 8. global max
    gmax_kernel<<<B_ * 32, 256>>>();
    // 9. per-batch glob MLP + g-part of head1 bias
    headg_kernel<<<B_, W2_>>>(glob_w, glob_b, head1_w, head1_b);
    // 10. head1: h = relu(f2 @ head1_w[0:256] + ghb[batch])
    {
        dim3 grid(W2_ / 64, PTS / 128);
        gemm_kernel<<<grid, 256>>>(f2, head1_w, nullptr, ghb, h, W2_, W2_, 1);
    }
    // 11. head2 + height bias
    head2_kernel<<<PTS / 4, 128>>>(head2_w, head2_b, x, thresh, sharp, scale, out);
}